// round 12
// baseline (speedup 1.0000x reference)
#include <cuda_runtime.h>
#include <math.h>

// Problem dims
#define Tt   257
#define Bb   16
#define Hh   1024
#define G4   4096
#define Ee   512
#define Ss   512
#define Vv   1024
#define MT   (Tt*Bb)        // 4112
#define SOS_TOK 1
#define EOS_TOK 2

#define STEP_BLOCKS 320     // 64 L0 (16 units) + 128 L1 (8 units) + 128 L2 (8 units)

typedef unsigned long long ull;

// ---------------- device scratch (no cudaMalloc allowed) ----------------
__device__ float d_xW0[(long long)MT*G4];    // [t*16+b][4096] = emb@Wih0^T
__device__ float d_hT[3][Hh*Bb];             // [k][b] hidden state per layer
__device__ float d_cS[3][Bb*Hh];             // [b][k] cell state per layer
__device__ float d_bias[3][G4];
__device__ float d_hs[(long long)MT*Hh];     // [b*257+t][1024]
__device__ float d_scores[(long long)Bb*Tt*Ss];
__device__ float d_ctx[(long long)MT*Hh];
__device__ float d_hidden[(long long)MT*Hh];
__device__ float d_logits[(long long)MT*Vv];

// ---------------- f32x2 helpers (Blackwell FFMA2) ----------------
__device__ __forceinline__ void ffma2(ull& d, ull a, ull b) {
    asm("fma.rn.f32x2 %0, %1, %2, %0;" : "+l"(d) : "l"(a), "l"(b));
}
__device__ __forceinline__ ull splat2(float x) {
    ull r; asm("mov.b64 %0, {%1, %1};" : "=l"(r) : "f"(x)); return r;
}
__device__ __forceinline__ float2 upk(ull v) {
    float2 r; asm("mov.b64 {%0, %1}, %2;" : "=f"(r.x), "=f"(r.y) : "l"(v)); return r;
}
__device__ __forceinline__ ull pack2(float a, float b) {
    ull r; asm("mov.b64 %0, {%1, %2};" : "=l"(r) : "f"(a), "f"(b)); return r;
}

// ---------------- init: zero states, fold biases, zero out ----------------
__global__ void k_init(const float* __restrict__ bih0, const float* __restrict__ bhh0,
                       const float* __restrict__ bih1, const float* __restrict__ bhh1,
                       const float* __restrict__ bih2, const float* __restrict__ bhh2,
                       float* out) {
    int i = blockIdx.x * 256 + threadIdx.x;
    if (i == 0) out[0] = 0.f;
    if (i < 3 * Hh * Bb) {
        ((float*)d_hT)[i] = 0.f;
        ((float*)d_cS)[i] = 0.f;
    }
    if (i < G4) {
        d_bias[0][i] = bih0[i] + bhh0[i];
        d_bias[1][i] = bih1[i] + bhh1[i];
        d_bias[2][i] = bih2[i] + bhh2[i];
    }
}

// ---------------- generic tiled GEMM: C[M][N] = epi(A @ B^T(+)) ----------------
template<int AMODE, int BMODE, int EPI>
__global__ __launch_bounds__(128, 2)
void k_gemm(const float* __restrict__ A, int lda, long long Az,
            const float* __restrict__ Bm, int ldb, long long Bz,
            float* __restrict__ C, int ldc, long long Cz,
            const float* __restrict__ bias,
            int M, int N, int K,
            const int* __restrict__ toks,
            const float* __restrict__ A2)
{
    __shared__ float As[16][72];
    __shared__ float Bs[16][136];
    int z = blockIdx.z;
    const float* Ab = A + Az * z;
    const float* Bv = Bm + Bz * z;
    float* Cb = C + Cz * z;
    int m0 = blockIdx.x * 64, n0 = blockIdx.y * 128;
    int tid = threadIdx.x;
    int tm = tid >> 4, tn = tid & 15;

    ull acc[4][8];
#pragma unroll
    for (int p = 0; p < 4; p++)
#pragma unroll
        for (int c = 0; c < 8; c++) acc[p][c] = 0ull;

    for (int kt = 0; kt < K; kt += 16) {
#pragma unroll
        for (int i = 0; i < 2; i++) {
            int id = tid * 2 + i;
            int r = id >> 2, kq = (id & 3) * 4;
            int row = m0 + r; if (row >= M) row = M - 1;
            float4 v;
            if (AMODE == 0) {
                v = *(const float4*)(Ab + (long long)row * lda + kt + kq);
            } else if (AMODE == 1) {
                int t = row >> 4, b = row & 15;
                int tok = (t == 0) ? SOS_TOK : toks[b * 256 + t - 1];
                v = *(const float4*)(Ab + (long long)tok * Ee + kt + kq);
            } else {
                int kk = kt + kq;
                const float* src = (kk < 1024) ? (A + (long long)row * 1024 + kk)
                                               : (A2 + (long long)row * 1024 + kk - 1024);
                v = *(const float4*)src;
            }
            As[kq + 0][r] = v.x; As[kq + 1][r] = v.y; As[kq + 2][r] = v.z; As[kq + 3][r] = v.w;
        }
        if (BMODE == 0) {
#pragma unroll
            for (int i = 0; i < 4; i++) {
                int id = tid * 4 + i;
                int n = id >> 2, kq = (id & 3) * 4;
                float4 v = *(const float4*)(Bv + (long long)(n0 + n) * ldb + kt + kq);
                Bs[kq + 0][n] = v.x; Bs[kq + 1][n] = v.y; Bs[kq + 2][n] = v.z; Bs[kq + 3][n] = v.w;
            }
        } else {
#pragma unroll
            for (int i = 0; i < 4; i++) {
                int id = tid * 4 + i;
                int kk = id >> 5, nq = (id & 31) * 4;
                float4 v = *(const float4*)(Bv + (long long)(kt + kk) * ldb + n0 + nq);
                *(float4*)&Bs[kk][nq] = v;
            }
        }
        __syncthreads();
#pragma unroll
        for (int k = 0; k < 16; k++) {
            float4 a0 = *(const float4*)&As[k][tm * 8];
            float4 a1 = *(const float4*)&As[k][tm * 8 + 4];
            ull pa[4];
            pa[0] = pack2(a0.x, a0.y); pa[1] = pack2(a0.z, a0.w);
            pa[2] = pack2(a1.x, a1.y); pa[3] = pack2(a1.z, a1.w);
            float4 b0 = *(const float4*)&Bs[k][tn * 8];
            float4 b1 = *(const float4*)&Bs[k][tn * 8 + 4];
            ull wb[8];
            wb[0] = splat2(b0.x); wb[1] = splat2(b0.y); wb[2] = splat2(b0.z); wb[3] = splat2(b0.w);
            wb[4] = splat2(b1.x); wb[5] = splat2(b1.y); wb[6] = splat2(b1.z); wb[7] = splat2(b1.w);
#pragma unroll
            for (int p = 0; p < 4; p++)
#pragma unroll
                for (int c = 0; c < 8; c++)
                    ffma2(acc[p][c], pa[p], wb[c]);
        }
        __syncthreads();
    }
    int ncol = n0 + tn * 8;
#pragma unroll
    for (int r = 0; r < 8; r++) {
        int row = m0 + tm * 8 + r;
        if (row < M) {
            float o[8];
#pragma unroll
            for (int c = 0; c < 8; c++) {
                float2 u = upk(acc[r >> 1][c]);
                o[c] = (r & 1) ? u.y : u.x;
            }
            if (EPI >= 1) {
#pragma unroll
                for (int c = 0; c < 8; c++) o[c] += bias[ncol + c];
            }
            if (EPI == 2) {
#pragma unroll
                for (int c = 0; c < 8; c++) o[c] = tanhf(o[c]);
            }
            *(float4*)(Cb + (long long)row * ldc + ncol)     = make_float4(o[0], o[1], o[2], o[3]);
            *(float4*)(Cb + (long long)row * ldc + ncol + 4) = make_float4(o[4], o[5], o[6], o[7]);
        }
    }
}

// ---------------- fused step kernel: one launch per wave, gates + cell ----------------
// Each block owns complete hidden units (all 4 gates, full K) -> cell fused, no partials.
// Warp = gate. L0: 64 blocks x 16 units, lanes = 16u x 2 b-halves, K=1024 (hh0).
// L1/L2: 128 blocks x 8 units, lanes = 8u x 4 b-quarters, K=2048 (ih + hh).
// W read directly in original [4096 rows][1024 k] layout (float4 over k, L1-cached).
__global__ __launch_bounds__(128)
void k_step(int w,
            const float* __restrict__ Whh0, const float* __restrict__ Wih1,
            const float* __restrict__ Whh1, const float* __restrict__ Wih2,
            const float* __restrict__ Whh2) {
    __shared__ float hsm[512 * 16];   // 32KB h chunk [k][b]
    __shared__ float sg[4 * 16 * 16]; // 4KB gate exchange [gate][u][b]
    int bid = blockIdx.x, tid = threadIdx.x;
    int gate = tid >> 5, lane = tid & 31;
    int layer, ublk;
    if (bid < 64)       { layer = 0; ublk = bid * 16; }
    else if (bid < 192) { layer = 1; ublk = (bid - 64) * 8; }
    else                { layer = 2; ublk = (bid - 192) * 8; }
    int t = w - layer;
    if (t < 0 || t >= Tt) return;

    if (layer == 0) {
        int u = lane & 15, bh = lane >> 4;       // 16 units x 2 b-halves
        int wrow = gate * 1024 + ublk + u;
        ull acc[4] = {0ull, 0ull, 0ull, 0ull};
        if (t > 0) {
            const float* hsrc = d_hT[0];
            const float* Wr = Whh0 + (long long)wrow * 1024;
#pragma unroll 1
            for (int ck = 0; ck < 1024; ck += 512) {
                const float4* Wp = (const float4*)(Wr + ck);
                float4 wb[8];
#pragma unroll
                for (int j = 0; j < 8; j++) wb[j] = Wp[j];   // overlap with staging
                __syncthreads();
                {
                    const float4* s = (const float4*)(hsrc + ck * 16);
                    float4* d4 = (float4*)hsm;
#pragma unroll
                    for (int i = 0; i < 16; i++) d4[tid + i * 128] = s[tid + i * 128];
                }
                __syncthreads();
#pragma unroll 1
                for (int kk = 0; kk < 512; kk += 32) {
#pragma unroll
                    for (int j = 0; j < 8; j++) {
                        float4 wv = wb[j];
                        int pi = (kk >> 2) + 8 + j; pi = min(pi, 127);
                        wb[j] = Wp[pi];
#pragma unroll
                        for (int q = 0; q < 4; q++) {
                            float ws = (q == 0) ? wv.x : (q == 1) ? wv.y : (q == 2) ? wv.z : wv.w;
                            ull wsp = splat2(ws);
                            const ulonglong2* hp =
                                (const ulonglong2*)(hsm + (kk + j * 4 + q) * 16) + bh * 2;
                            ulonglong2 h01 = hp[0], h23 = hp[1];
                            ffma2(acc[0], h01.x, wsp);
                            ffma2(acc[1], h01.y, wsp);
                            ffma2(acc[2], h23.x, wsp);
                            ffma2(acc[3], h23.y, wsp);
                        }
                    }
                }
            }
            __syncthreads();   // hsm reuse done
        }
        // exchange gate pre-activations
        {
            float* sp = sg + (gate * 16 + u) * 16 + bh * 8;
#pragma unroll
            for (int p = 0; p < 4; p++) { float2 v = upk(acc[p]); sp[2 * p] = v.x; sp[2 * p + 1] = v.y; }
        }
        __syncthreads();
        // cell: 256 cells, 2 per thread
        {
            int u2 = tid >> 3, bb = (tid & 7) * 2;
#pragma unroll
            for (int cc = 0; cc < 2; cc++) {
                int b = bb + cc;
                int kg = ublk + u2;
                float pre[4];
#pragma unroll
                for (int gi = 0; gi < 4; gi++)
                    pre[gi] = sg[(gi * 16 + u2) * 16 + b] + d_bias[0][gi * 1024 + kg]
                            + d_xW0[((long long)(t * 16 + b)) * G4 + gi * 1024 + kg];
                float i_ = 1.f / (1.f + __expf(-pre[0]));
                float f_ = 1.f / (1.f + __expf(-pre[1]));
                float g_ = tanhf(pre[2]);
                float o_ = 1.f / (1.f + __expf(-pre[3]));
                float c = f_ * d_cS[0][b * 1024 + kg] + i_ * g_;
                d_cS[0][b * 1024 + kg] = c;
                d_hT[0][kg * 16 + b] = o_ * tanhf(c);
            }
        }
    } else {
        int u = lane & 7, bq = lane >> 3;        // 8 units x 4 b-quarters
        int wrow = gate * 1024 + ublk + u;
        const float* Wih = (layer == 1) ? Wih1 : Wih2;
        const float* Whh = (layer == 1) ? Whh1 : Whh2;
        ull acc[2] = {0ull, 0ull};
#pragma unroll 1
        for (int term = 0; term < 2; term++) {
            if (term == 1 && t == 0) break;      // hh input all-zero at first step
            const float* hsrc = (term == 0) ? d_hT[layer - 1] : d_hT[layer];
            const float* Wr = ((term == 0) ? Wih : Whh) + (long long)wrow * 1024;
#pragma unroll 1
            for (int ck = 0; ck < 1024; ck += 512) {
                const float4* Wp = (const float4*)(Wr + ck);
                float4 wb[8];
#pragma unroll
                for (int j = 0; j < 8; j++) wb[j] = Wp[j];
                __syncthreads();
                {
                    const float4* s = (const float4*)(hsrc + ck * 16);
                    float4* d4 = (float4*)hsm;
#pragma unroll
                    for (int i = 0; i < 16; i++) d4[tid + i * 128] = s[tid + i * 128];
                }
                __syncthreads();
#pragma unroll 1
                for (int kk = 0; kk < 512; kk += 32) {
#pragma unroll
                    for (int j = 0; j < 8; j++) {
                        float4 wv = wb[j];
                        int pi = (kk >> 2) + 8 + j; pi = min(pi, 127);
                        wb[j] = Wp[pi];
#pragma unroll
                        for (int q = 0; q < 4; q++) {
                            float ws = (q == 0) ? wv.x : (q == 1) ? wv.y : (q == 2) ? wv.z : wv.w;
                            ull wsp = splat2(ws);
                            const ulonglong2* hp =
                                (const ulonglong2*)(hsm + (kk + j * 4 + q) * 16) + bq;
                            ulonglong2 h01 = hp[0];
                            ffma2(acc[0], h01.x, wsp);
                            ffma2(acc[1], h01.y, wsp);
                        }
                    }
                }
            }
        }
        __syncthreads();
        {
            float* sp = sg + (gate * 8 + u) * 16 + bq * 4;
            float2 v0 = upk(acc[0]), v1 = upk(acc[1]);
            sp[0] = v0.x; sp[1] = v0.y; sp[2] = v1.x; sp[3] = v1.y;
        }
        __syncthreads();
        // cell: 128 cells, 1 per thread
        {
            int u2 = tid >> 4, b = tid & 15;
            int kg = ublk + u2;
            float pre[4];
#pragma unroll
            for (int gi = 0; gi < 4; gi++)
                pre[gi] = sg[(gi * 8 + u2) * 16 + b] + d_bias[layer][gi * 1024 + kg];
            float i_ = 1.f / (1.f + __expf(-pre[0]));
            float f_ = 1.f / (1.f + __expf(-pre[1]));
            float g_ = tanhf(pre[2]);
            float o_ = 1.f / (1.f + __expf(-pre[3]));
            float c = f_ * d_cS[layer][b * 1024 + kg] + i_ * g_;
            d_cS[layer][b * 1024 + kg] = c;
            float h = o_ * tanhf(c);
            d_hT[layer][kg * 16 + b] = h;
            if (layer == 2) d_hs[((long long)b * Tt + t) * 1024 + kg] = h;
        }
    }
}

// ---------------- softmax over attention scores (in place) ----------------
__global__ void k_softmax(float* __restrict__ sc) {
    long long row = blockIdx.x;
    float* p = sc + row * Ss;
    int tid = threadIdx.x;  // 128
    __shared__ float red[4], red2[4];
    float mx = -1e30f;
    float vals[4];
#pragma unroll
    for (int j = 0; j < 4; j++) { vals[j] = p[tid + j * 128]; mx = fmaxf(mx, vals[j]); }
#pragma unroll
    for (int o = 16; o; o >>= 1) mx = fmaxf(mx, __shfl_xor_sync(0xffffffffu, mx, o));
    if ((tid & 31) == 0) red[tid >> 5] = mx;
    __syncthreads();
    mx = fmaxf(fmaxf(red[0], red[1]), fmaxf(red[2], red[3]));
    float s = 0.f;
#pragma unroll
    for (int j = 0; j < 4; j++) { vals[j] = __expf(vals[j] - mx); s += vals[j]; }
#pragma unroll
    for (int o = 16; o; o >>= 1) s += __shfl_xor_sync(0xffffffffu, s, o);
    if ((tid & 31) == 0) red2[tid >> 5] = s;
    __syncthreads();
    s = red2[0] + red2[1] + red2[2] + red2[3];
    float inv = 1.f / s;
#pragma unroll
    for (int j = 0; j < 4; j++) p[tid + j * 128] = vals[j] * inv;
}

// ---------------- loss ----------------
__global__ void k_loss(const int* __restrict__ toks, float* __restrict__ out) {
    int m = blockIdx.x;             // b*257 + t
    int b = m / Tt, t = m % Tt;
    const float* p = d_logits + (long long)m * Vv;
    int tid = threadIdx.x;          // 256
    __shared__ float red[8];
    float mx = -1e30f;
    float v[4];
#pragma unroll
    for (int j = 0; j < 4; j++) { v[j] = p[tid + j * 256]; mx = fmaxf(mx, v[j]); }
#pragma unroll
    for (int o = 16; o; o >>= 1) mx = fmaxf(mx, __shfl_xor_sync(0xffffffffu, mx, o));
    if ((tid & 31) == 0) red[tid >> 5] = mx;
    __syncthreads();
    mx = red[0];
#pragma unroll
    for (int i = 1; i < 8; i++) mx = fmaxf(mx, red[i]);
    __syncthreads();
    float s = 0.f;
#pragma unroll
    for (int j = 0; j < 4; j++) s += __expf(v[j] - mx);
#pragma unroll
    for (int o = 16; o; o >>= 1) s += __shfl_xor_sync(0xffffffffu, s, o);
    if ((tid & 31) == 0) red[tid >> 5] = s;
    __syncthreads();
    if (tid == 0) {
        float tot = 0.f;
#pragma unroll
        for (int i = 0; i < 8; i++) tot += red[i];
        int tgt = (t < 256) ? toks[b * 256 + t] : EOS_TOK;
        float nll = logf(tot) + mx - p[tgt];
        atomicAdd(out, nll * (1.f / (float)MT));
    }
}

// ---------------- host launch ----------------
extern "C" void kernel_launch(void* const* d_in, const int* in_sizes, int n_in,
                              void* d_out, int out_size) {
    const int*   tokens = (const int*)d_in[0];
    const float* enc    = (const float*)d_in[1];
    const float* emb    = (const float*)d_in[2];
    const float* Wih0   = (const float*)d_in[3];
    const float* Whh0   = (const float*)d_in[4];
    const float* bih0   = (const float*)d_in[5];
    const float* bhh0   = (const float*)d_in[6];
    const float* Wih1   = (const float*)d_in[7];
    const float* Whh1   = (const float*)d_in[8];
    const float* bih1   = (const float*)d_in[9];
    const float* bhh1   = (const float*)d_in[10];
    const float* Wih2   = (const float*)d_in[11];
    const float* Whh2   = (const float*)d_in[12];
    const float* bih2   = (const float*)d_in[13];
    const float* bhh2   = (const float*)d_in[14];
    const float* W1     = (const float*)d_in[15];
    const float* b1     = (const float*)d_in[16];
    const float* W2     = (const float*)d_in[17];
    const float* b2     = (const float*)d_in[18];
    float* out = (float*)d_out;

    float *p_xW0, *p_hs, *p_scores, *p_ctx, *p_hidden, *p_logits;
    cudaGetSymbolAddress((void**)&p_xW0,    d_xW0);
    cudaGetSymbolAddress((void**)&p_hs,     d_hs);
    cudaGetSymbolAddress((void**)&p_scores, d_scores);
    cudaGetSymbolAddress((void**)&p_ctx,    d_ctx);
    cudaGetSymbolAddress((void**)&p_hidden, d_hidden);
    cudaGetSymbolAddress((void**)&p_logits, d_logits);

    // launch 0: init states + biases + out
    k_init<<<192, 256>>>(bih0, bhh0, bih1, bhh1, bih2, bhh2, out);

    // launch 1: xW0 = emb(dec_in) @ W_ih0[:, :512]^T
    k_gemm<1, 0, 0><<<dim3(65, 32, 1), 128>>>(emb, Ee, 0,
                                              Wih0, Ee + 1024, 0,
                                              p_xW0, G4, 0,
                                              nullptr, MT, G4, Ee, tokens, nullptr);

    // recurrence: 259 fused step launches (gates + cell, no partials)
    for (int w = 0; w < Tt + 2; w++) {
        k_step<<<STEP_BLOCKS, 128>>>(w, Whh0, Wih1, Whh1, Wih2, Whh2);
    }

    // attention scores: per b, hs[257,1024] @ enc_b[512,1024]^T
    k_gemm<0, 0, 0><<<dim3(5, 4, 16), 128>>>(p_hs, Hh, (long long)Tt * Hh,
                                             enc, Hh, (long long)Ss * Hh,
                                             p_scores, Ss, (long long)Tt * Ss,
                                             nullptr, Tt, Ss, Hh, nullptr, nullptr);
    k_softmax<<<MT, 128>>>(p_scores);
    // ctx: attn[257,512] @ enc_b[512,1024]  (NN)
    k_gemm<0, 1, 0><<<dim3(5, 8, 16), 128>>>(p_scores, Ss, (long long)Tt * Ss,
                                             enc, Hh, (long long)Ss * Hh,
                                             p_ctx, Hh, (long long)Tt * Hh,
                                             nullptr, Tt, Hh, Ss, nullptr, nullptr);
    // hidden = tanh(concat(hs,ctx) @ W1^T + b1)
    k_gemm<2, 0, 2><<<dim3(65, 8, 1), 128>>>(p_hs, 2048, 0,
                                             W1, 2048, 0,
                                             p_hidden, Hh, 0,
                                             b1, MT, Hh, 2048, nullptr, p_ctx);
    // logits = hidden @ W2^T + b2
    k_gemm<0, 0, 1><<<dim3(65, 8, 1), 128>>>(p_hidden, Hh, 0,
                                             W2, Hh, 0,
                                             p_logits, Vv, 0,
                                             b2, MT, Vv, Hh, nullptr, nullptr);
    // loss
    k_loss<<<MT, 256>>>(tokens, out);
}

// round 14
// speedup vs baseline: 4.9618x; 4.9618x over previous
#include <cuda_runtime.h>
#include <math.h>

// Problem dims
#define Tt   257
#define Bb   16
#define Hh   1024
#define G4   4096
#define Ee   512
#define Ss   512
#define Vv   1024
#define MT   (Tt*Bb)        // 4112
#define SOS_TOK 1
#define EOS_TOK 2

#define GATE_BLOCKS 296     // 37 slots x 8 colTiles (R8 decomposition)

typedef unsigned long long ull;

// ---------------- device scratch (no cudaMalloc allowed) ----------------
#define WROWS 1032
__device__ float d_WT[5][WROWS*G4];      // transposed weights [k][g]: 0=hh0 1=ih1 2=hh1 3=ih2 4=hh2
__device__ float d_xW0[(long long)MT*G4];// [t*16+b][4096]
__device__ float d_hT[3][Hh*Bb];         // [k][b] transposed hidden state per layer
__device__ float d_cS[3][Bb*Hh];         // [b][k] cell state per layer
__device__ float d_bias[3][G4];
__device__ float d_part[37][Bb*G4];      // K-split partials [slot][b][col]
__device__ float d_hs[(long long)MT*Hh];     // [b*257+t][1024]
__device__ float d_scores[(long long)Bb*Tt*Ss];
__device__ float d_ctx[(long long)MT*Hh];
__device__ float d_hidden[(long long)MT*Hh];
__device__ float d_logits[(long long)MT*Vv];

// ---------------- f32x2 helpers (Blackwell FFMA2; used by k_gemm) ----------------
__device__ __forceinline__ void ffma2(ull& d, ull a, ull b) {
    asm("fma.rn.f32x2 %0, %1, %2, %0;" : "+l"(d) : "l"(a), "l"(b));
}
__device__ __forceinline__ ull splat2(float x) {
    ull r; asm("mov.b64 %0, {%1, %1};" : "=l"(r) : "f"(x)); return r;
}
__device__ __forceinline__ float2 upk(ull v) {
    float2 r; asm("mov.b64 {%0, %1}, %2;" : "=f"(r.x), "=f"(r.y) : "l"(v)); return r;
}
__device__ __forceinline__ ull pack2(float a, float b) {
    ull r; asm("mov.b64 %0, {%1, %2};" : "=l"(r) : "f"(a), "f"(b)); return r;
}

// ---------------- init: zero states, fold biases, zero out ----------------
__global__ void k_init(const float* __restrict__ bih0, const float* __restrict__ bhh0,
                       const float* __restrict__ bih1, const float* __restrict__ bhh1,
                       const float* __restrict__ bih2, const float* __restrict__ bhh2,
                       float* out) {
    int i = blockIdx.x * 256 + threadIdx.x;
    if (i == 0) out[0] = 0.f;
    if (i < 3 * Hh * Bb) {
        ((float*)d_hT)[i] = 0.f;
        ((float*)d_cS)[i] = 0.f;
    }
    if (i < G4) {
        d_bias[0][i] = bih0[i] + bhh0[i];
        d_bias[1][i] = bih1[i] + bhh1[i];
        d_bias[2][i] = bih2[i] + bhh2[i];
    }
}

// ---------------- transpose all 5 W [4096][1024] -> WT [k][4096] (one launch) ----------------
__global__ void k_transpose_all(const float* __restrict__ s0, const float* __restrict__ s1,
                                const float* __restrict__ s2, const float* __restrict__ s3,
                                const float* __restrict__ s4) {
    __shared__ float t[32][33];
    int z = blockIdx.z;
    const float* src = (z == 0) ? s0 : (z == 1) ? s1 : (z == 2) ? s2 : (z == 3) ? s3 : s4;
    float* dst = d_WT[z];
    int k0 = blockIdx.x * 32, g0 = blockIdx.y * 32;
    int x = threadIdx.x, y = threadIdx.y;  // block (32,8)
#pragma unroll
    for (int j = 0; j < 32; j += 8)
        t[y + j][x] = src[(long long)(g0 + y + j) * 1024 + k0 + x];
    __syncthreads();
#pragma unroll
    for (int j = 0; j < 32; j += 8)
        dst[(long long)(k0 + y + j) * G4 + g0 + x] = t[x][y + j];
}

// ---------------- generic tiled GEMM: C[M][N] = epi(A @ B^T(+)) ----------------
template<int AMODE, int BMODE, int EPI>
__global__ __launch_bounds__(128, 2)
void k_gemm(const float* __restrict__ A, int lda, long long Az,
            const float* __restrict__ Bm, int ldb, long long Bz,
            float* __restrict__ C, int ldc, long long Cz,
            const float* __restrict__ bias,
            int M, int N, int K,
            const int* __restrict__ toks,
            const float* __restrict__ A2)
{
    __shared__ float As[16][72];
    __shared__ float Bs[16][136];
    int z = blockIdx.z;
    const float* Ab = A + Az * z;
    const float* Bv = Bm + Bz * z;
    float* Cb = C + Cz * z;
    int m0 = blockIdx.x * 64, n0 = blockIdx.y * 128;
    int tid = threadIdx.x;
    int tm = tid >> 4, tn = tid & 15;

    ull acc[4][8];
#pragma unroll
    for (int p = 0; p < 4; p++)
#pragma unroll
        for (int c = 0; c < 8; c++) acc[p][c] = 0ull;

    for (int kt = 0; kt < K; kt += 16) {
#pragma unroll
        for (int i = 0; i < 2; i++) {
            int id = tid * 2 + i;
            int r = id >> 2, kq = (id & 3) * 4;
            int row = m0 + r; if (row >= M) row = M - 1;
            float4 v;
            if (AMODE == 0) {
                v = *(const float4*)(Ab + (long long)row * lda + kt + kq);
            } else if (AMODE == 1) {
                int t = row >> 4, b = row & 15;
                int tok = (t == 0) ? SOS_TOK : toks[b * 256 + t - 1];
                v = *(const float4*)(Ab + (long long)tok * Ee + kt + kq);
            } else {
                int kk = kt + kq;
                const float* src = (kk < 1024) ? (A + (long long)row * 1024 + kk)
                                               : (A2 + (long long)row * 1024 + kk - 1024);
                v = *(const float4*)src;
            }
            As[kq + 0][r] = v.x; As[kq + 1][r] = v.y; As[kq + 2][r] = v.z; As[kq + 3][r] = v.w;
        }
        if (BMODE == 0) {
#pragma unroll
            for (int i = 0; i < 4; i++) {
                int id = tid * 4 + i;
                int n = id >> 2, kq = (id & 3) * 4;
                float4 v = *(const float4*)(Bv + (long long)(n0 + n) * ldb + kt + kq);
                Bs[kq + 0][n] = v.x; Bs[kq + 1][n] = v.y; Bs[kq + 2][n] = v.z; Bs[kq + 3][n] = v.w;
            }
        } else {
#pragma unroll
            for (int i = 0; i < 4; i++) {
                int id = tid * 4 + i;
                int kk = id >> 5, nq = (id & 31) * 4;
                float4 v = *(const float4*)(Bv + (long long)(kt + kk) * ldb + n0 + nq);
                *(float4*)&Bs[kk][nq] = v;
            }
        }
        __syncthreads();
#pragma unroll
        for (int k = 0; k < 16; k++) {
            float4 a0 = *(const float4*)&As[k][tm * 8];
            float4 a1 = *(const float4*)&As[k][tm * 8 + 4];
            ull pa[4];
            pa[0] = pack2(a0.x, a0.y); pa[1] = pack2(a0.z, a0.w);
            pa[2] = pack2(a1.x, a1.y); pa[3] = pack2(a1.z, a1.w);
            float4 b0 = *(const float4*)&Bs[k][tn * 8];
            float4 b1 = *(const float4*)&Bs[k][tn * 8 + 4];
            ull wb[8];
            wb[0] = splat2(b0.x); wb[1] = splat2(b0.y); wb[2] = splat2(b0.z); wb[3] = splat2(b0.w);
            wb[4] = splat2(b1.x); wb[5] = splat2(b1.y); wb[6] = splat2(b1.z); wb[7] = splat2(b1.w);
#pragma unroll
            for (int p = 0; p < 4; p++)
#pragma unroll
                for (int c = 0; c < 8; c++)
                    ffma2(acc[p][c], pa[p], wb[c]);
        }
        __syncthreads();
    }
    int ncol = n0 + tn * 8;
#pragma unroll
    for (int r = 0; r < 8; r++) {
        int row = m0 + tm * 8 + r;
        if (row < M) {
            float o[8];
#pragma unroll
            for (int c = 0; c < 8; c++) {
                float2 u = upk(acc[r >> 1][c]);
                o[c] = (r & 1) ? u.y : u.x;
            }
            if (EPI >= 1) {
#pragma unroll
                for (int c = 0; c < 8; c++) o[c] += bias[ncol + c];
            }
            if (EPI == 2) {
#pragma unroll
                for (int c = 0; c < 8; c++) o[c] = tanhf(o[c]);
            }
            *(float4*)(Cb + (long long)row * ldc + ncol)     = make_float4(o[0], o[1], o[2], o[3]);
            *(float4*)(Cb + (long long)row * ldc + ncol + 4) = make_float4(o[4], o[5], o[6], o[7]);
        }
    }
}

// ---------------- recurrence: gates via mma.sync tf32 (per-wave launch) ----------------
// Grid = R8: 296 blocks = 37 (term,kChunk) slots x 8 colTiles. kLen in {128,144,152}, all %8==0.
// Per block: D[512 gate-cols][16 batch] partial over kLen. mma.m16n8k8: M=16 batch (A=h),
// N=8 gate-cols (B=W from SMEM slab), fp32 accum. W double-buffered in 8k x 520 slabs.
__global__ __launch_bounds__(128, 2)
void k_gates(int w) {
    int slot = blockIdx.x >> 3;      // 0..36
    int ct   = blockIdx.x & 7;       // colTile (512 cols)
    int term, ci;
    if (slot < 8)       { term = 0; ci = slot; }
    else if (slot < 15) { term = 1; ci = slot - 8; }
    else if (slot < 22) { term = 2; ci = slot - 15; }
    else if (slot < 29) { term = 3; ci = slot - 22; }
    else                { term = 4; ci = slot - 29; }
    int k0, kLen;
    if (term == 0 || term == 4) { k0 = ci * 128; kLen = 128; }
    else {
        if (ci < 5) { k0 = ci * 144; kLen = 144; }
        else        { k0 = 720 + (ci - 5) * 152; kLen = 152; }
    }
    int layer = (term == 0) ? 0 : (term <= 2 ? 1 : 2);
    int t = w - layer;
    if (t < 0 || t >= Tt) return;

    int tid = threadIdx.x;
    int warp = tid >> 5, lane = tid & 31;

    // hh-term input all-zero at first step of its layer: write zero partials
    bool zeroIn = (term == 0 || term == 2 || term == 4) && (w == layer);
    if (zeroIn) {
        int c0 = ct * 512 + warp * 128 + lane * 4;
        float* dst = d_part[slot];
        float4 z = make_float4(0.f, 0.f, 0.f, 0.f);
#pragma unroll
        for (int b = 0; b < 16; b++) *(float4*)(dst + b * G4 + c0) = z;
        return;
    }

    int hidx = (term == 0) ? 0 : (term == 1) ? 0 : (term == 2) ? 1 : (term == 3) ? 1 : 2;
    const float* hsrc = d_hT[hidx];

    __shared__ __align__(16) float hs_sm[152 * 16];   // 9.5 KB, [k][b]
    __shared__ __align__(16) float Wsm[2][8 * 520];   // 33.3 KB, [slab][k][g(+pad)]
    {
        const float4* src = (const float4*)(hsrc + k0 * 16);
        float4* dst4 = (float4*)hs_sm;
        int n4 = kLen * 4;
        for (int i = tid; i < n4; i += 128) dst4[i] = src[i];
    }

    int gid = lane >> 2, tig = lane & 3;   // mma groupID / threadID_in_group
    float dacc[16][4];
#pragma unroll
    for (int nt = 0; nt < 16; nt++)
#pragma unroll
        for (int c = 0; c < 4; c++) dacc[nt][c] = 0.f;

    const float* Wbase = d_WT[term] + (long long)k0 * G4 + ct * 512;
    int nslab = kLen >> 3;
    // slab load: 8 k-rows x 512 cols, coalesced float4 (kr = tid>>4, 16 threads per k-row)
    {
        int kr = tid >> 4, ii = tid & 15;
        const float4* src = (const float4*)(Wbase + (long long)kr * G4);
        float4* dstp = (float4*)(&Wsm[0][kr * 520]);
#pragma unroll
        for (int j = 0; j < 8; j++) dstp[ii + j * 16] = src[ii + j * 16];
    }
    __syncthreads();

    for (int s = 0; s < nslab; s++) {
        if (s + 1 < nslab) {
            int kr = tid >> 4, ii = tid & 15;
            const float4* src = (const float4*)(Wbase + (long long)((s + 1) * 8 + kr) * G4);
            float4* dstp = (float4*)(&Wsm[(s + 1) & 1][kr * 520]);
#pragma unroll
            for (int j = 0; j < 8; j++) dstp[ii + j * 16] = src[ii + j * 16];
        }
        const float* Wb = Wsm[s & 1];
        int kb = s * 8;
        // A fragments (h): A[m=batch][k], row-major
        unsigned a0 = __float_as_uint(hs_sm[(kb + tig) * 16 + gid]);
        unsigned a1 = __float_as_uint(hs_sm[(kb + tig) * 16 + gid + 8]);
        unsigned a2 = __float_as_uint(hs_sm[(kb + tig + 4) * 16 + gid]);
        unsigned a3 = __float_as_uint(hs_sm[(kb + tig + 4) * 16 + gid + 8]);
#pragma unroll
        for (int nt = 0; nt < 16; nt++) {
            int g = warp * 128 + nt * 8 + gid;
            unsigned b0 = __float_as_uint(Wb[tig * 520 + g]);
            unsigned b1 = __float_as_uint(Wb[(tig + 4) * 520 + g]);
            asm volatile(
                "mma.sync.aligned.m16n8k8.row.col.f32.tf32.tf32.f32 "
                "{%0,%1,%2,%3}, {%4,%5,%6,%7}, {%8,%9}, {%0,%1,%2,%3};"
                : "+f"(dacc[nt][0]), "+f"(dacc[nt][1]), "+f"(dacc[nt][2]), "+f"(dacc[nt][3])
                : "r"(a0), "r"(a1), "r"(a2), "r"(a3), "r"(b0), "r"(b1));
        }
        __syncthreads();
    }

    // epilogue: D[m=batch][n=gate-col] -> d_part[slot][b*4096 + col]
    float* dst = d_part[slot];
#pragma unroll
    for (int nt = 0; nt < 16; nt++) {
        int col = ct * 512 + warp * 128 + nt * 8 + tig * 2;
        *(float2*)(dst + (long long)gid * G4 + col)       = make_float2(dacc[nt][0], dacc[nt][1]);
        *(float2*)(dst + (long long)(gid + 8) * G4 + col) = make_float2(dacc[nt][2], dacc[nt][3]);
    }
}

// ---------------- recurrence: cell (reduce partials, activations, state update) ----------------
__global__ void k_cell(int w) {
    int bx = blockIdx.x;
    int layer = bx >> 6, chunk = bx & 63;
    int t = w - layer;
    if (t < 0 || t >= Tt) return;
    int cid = chunk * 256 + threadIdx.x;
    int b = cid >> 10, k = cid & 1023;

    int s0, ns;
    if (layer == 0)      { s0 = 0;  ns = 8; }
    else if (layer == 1) { s0 = 8;  ns = 14; }
    else                 { s0 = 22; ns = 15; }

    float gv[4];
#pragma unroll
    for (int gi = 0; gi < 4; gi++) {
        int col = k + (gi << 10);
        float v = d_bias[layer][col];
        if (layer == 0) v += d_xW0[((long long)(t * 16 + b)) * G4 + col];
        for (int s = 0; s < ns; s++) v += d_part[s0 + s][b * G4 + col];
        gv[gi] = v;
    }
    float i_ = 1.f / (1.f + __expf(-gv[0]));
    float f_ = 1.f / (1.f + __expf(-gv[1]));
    float g_ = tanhf(gv[2]);
    float o_ = 1.f / (1.f + __expf(-gv[3]));
    float c = f_ * d_cS[layer][b * 1024 + k] + i_ * g_;
    d_cS[layer][b * 1024 + k] = c;
    float h = o_ * tanhf(c);
    d_hT[layer][k * 16 + b] = h;
    if (layer == 2) d_hs[((long long)b * Tt + t) * 1024 + k] = h;
}

// ---------------- softmax over attention scores (in place) ----------------
__global__ void k_softmax(float* __restrict__ sc) {
    long long row = blockIdx.x;
    float* p = sc + row * Ss;
    int tid = threadIdx.x;  // 128
    __shared__ float red[4], red2[4];
    float mx = -1e30f;
    float vals[4];
#pragma unroll
    for (int j = 0; j < 4; j++) { vals[j] = p[tid + j * 128]; mx = fmaxf(mx, vals[j]); }
#pragma unroll
    for (int o = 16; o; o >>= 1) mx = fmaxf(mx, __shfl_xor_sync(0xffffffffu, mx, o));
    if ((tid & 31) == 0) red[tid >> 5] = mx;
    __syncthreads();
    mx = fmaxf(fmaxf(red[0], red[1]), fmaxf(red[2], red[3]));
    float s = 0.f;
#pragma unroll
    for (int j = 0; j < 4; j++) { vals[j] = __expf(vals[j] - mx); s += vals[j]; }
#pragma unroll
    for (int o = 16; o; o >>= 1) s += __shfl_xor_sync(0xffffffffu, s, o);
    if ((tid & 31) == 0) red2[tid >> 5] = s;
    __syncthreads();
    s = red2[0] + red2[1] + red2[2] + red2[3];
    float inv = 1.f / s;
#pragma unroll
    for (int j = 0; j < 4; j++) p[tid + j * 128] = vals[j] * inv;
}

// ---------------- loss ----------------
__global__ void k_loss(const int* __restrict__ toks, float* __restrict__ out) {
    int m = blockIdx.x;             // b*257 + t
    int b = m / Tt, t = m % Tt;
    const float* p = d_logits + (long long)m * Vv;
    int tid = threadIdx.x;          // 256
    __shared__ float red[8];
    float mx = -1e30f;
    float v[4];
#pragma unroll
    for (int j = 0; j < 4; j++) { v[j] = p[tid + j * 256]; mx = fmaxf(mx, v[j]); }
#pragma unroll
    for (int o = 16; o; o >>= 1) mx = fmaxf(mx, __shfl_xor_sync(0xffffffffu, mx, o));
    if ((tid & 31) == 0) red[tid >> 5] = mx;
    __syncthreads();
    mx = red[0];
#pragma unroll
    for (int i = 1; i < 8; i++) mx = fmaxf(mx, red[i]);
    __syncthreads();
    float s = 0.f;
#pragma unroll
    for (int j = 0; j < 4; j++) s += __expf(v[j] - mx);
#pragma unroll
    for (int o = 16; o; o >>= 1) s += __shfl_xor_sync(0xffffffffu, s, o);
    if ((tid & 31) == 0) red[tid >> 5] = s;
    __syncthreads();
    if (tid == 0) {
        float tot = 0.f;
#pragma unroll
        for (int i = 0; i < 8; i++) tot += red[i];
        int tgt = (t < 256) ? toks[b * 256 + t] : EOS_TOK;
        float nll = logf(tot) + mx - p[tgt];
        atomicAdd(out, nll * (1.f / (float)MT));
    }
}

// ---------------- host launch ----------------
extern "C" void kernel_launch(void* const* d_in, const int* in_sizes, int n_in,
                              void* d_out, int out_size) {
    const int*   tokens = (const int*)d_in[0];
    const float* enc    = (const float*)d_in[1];
    const float* emb    = (const float*)d_in[2];
    const float* Wih0   = (const float*)d_in[3];
    const float* Whh0   = (const float*)d_in[4];
    const float* bih0   = (const float*)d_in[5];
    const float* bhh0   = (const float*)d_in[6];
    const float* Wih1   = (const float*)d_in[7];
    const float* Whh1   = (const float*)d_in[8];
    const float* bih1   = (const float*)d_in[9];
    const float* bhh1   = (const float*)d_in[10];
    const float* Wih2   = (const float*)d_in[11];
    const float* Whh2   = (const float*)d_in[12];
    const float* bih2   = (const float*)d_in[13];
    const float* bhh2   = (const float*)d_in[14];
    const float* W1     = (const float*)d_in[15];
    const float* b1     = (const float*)d_in[16];
    const float* W2     = (const float*)d_in[17];
    const float* b2     = (const float*)d_in[18];
    float* out = (float*)d_out;

    float *p_xW0, *p_hs, *p_scores, *p_ctx, *p_hidden, *p_logits;
    cudaGetSymbolAddress((void**)&p_xW0,    d_xW0);
    cudaGetSymbolAddress((void**)&p_hs,     d_hs);
    cudaGetSymbolAddress((void**)&p_scores, d_scores);
    cudaGetSymbolAddress((void**)&p_ctx,    d_ctx);
    cudaGetSymbolAddress((void**)&p_hidden, d_hidden);
    cudaGetSymbolAddress((void**)&p_logits, d_logits);

    // launch #1: init states + biases + out
    k_init<<<192, 256>>>(bih0, bhh0, bih1, bhh1, bih2, bhh2, out);

    // launch #2: all weight transposes in one kernel
    k_transpose_all<<<dim3(32, 128, 5), dim3(32, 8)>>>(Whh0, Wih1, Whh1, Wih2, Whh2);

    // launch #3: xW0 = emb(dec_in) @ W_ih0[:, :512]^T
    k_gemm<1, 0, 0><<<dim3(65, 32, 1), 128>>>(emb, Ee, 0,
                                              Wih0, Ee + 1024, 0,
                                              p_xW0, G4, 0,
                                              nullptr, MT, G4, Ee, tokens, nullptr);

    // recurrence: 259 waves, 2 launches each (gates now tensor-core tf32)
    for (int w = 0; w < Tt + 2; w++) {
        k_gates<<<GATE_BLOCKS, 128>>>(w);
        k_cell<<<192, 256>>>(w);
    }

    // attention scores: per b, hs[257,1024] @ enc_b[512,1024]^T
    k_gemm<0, 0, 0><<<dim3(5, 4, 16), 128>>>(p_hs, Hh, (long long)Tt * Hh,
                                             enc, Hh, (long long)Ss * Hh,
                                             p_scores, Ss, (long long)Tt * Ss,
                                             nullptr, Tt, Ss, Hh, nullptr, nullptr);
    k_softmax<<<MT, 128>>>(p_scores);
    // ctx: attn[257,512] @ enc_b[512,1024]  (NN)
    k_gemm<0, 1, 0><<<dim3(5, 8, 16), 128>>>(p_scores, Ss, (long long)Tt * Ss,
                                             enc, Hh, (long long)Ss * Hh,
                                             p_ctx, Hh, (long long)Tt * Hh,
                                             nullptr, Tt, Hh, Ss, nullptr, nullptr);
    // hidden = tanh(concat(hs,ctx) @ W1^T + b1)
    k_gemm<2, 0, 2><<<dim3(65, 8, 1), 128>>>(p_hs, 2048, 0,
                                             W1, 2048, 0,
                                             p_hidden, Hh, 0,
                                             b1, MT, Hh, 2048, nullptr, p_ctx);
    // logits = hidden @ W2^T + b2
    k_gemm<0, 0, 1><<<dim3(65, 8, 1), 128>>>(p_hidden, Hh, 0,
                                             W2, Hh, 0,
                                             p_logits, Vv, 0,
                                             b2, MT, Vv, Hh, nullptr, nullptr);
    // loss
    k_loss<<<MT, 256>>>(tokens, out);
}